// round 1
// baseline (speedup 1.0000x reference)
#include <cuda_runtime.h>

#define Dm 256
#define MAXB 4096

// Scratch (no allocations allowed): per-batch meta projection + fused square table.
__device__ float g_meta[MAXB * Dm];   // 4 MB
__device__ float g_pre[64 * Dm];      // 64 KB: emb*scale + bias

// ---------------------------------------------------------------------------
// Kernel 0: pre[s,d] = emb[s,d]*scale[s,d] + bias[s,d]   (16384 elements)
// ---------------------------------------------------------------------------
__global__ void pre_kernel(const float* __restrict__ emb,
                           const float* __restrict__ sc,
                           const float* __restrict__ bi) {
    int i = blockIdx.x * 256 + threadIdx.x;
    g_pre[i] = fmaf(emb[i], sc[i], bi[i]);
}

// ---------------------------------------------------------------------------
// Kernel 1: g_meta[b,d] = meta[b,0:28] @ W_meta[28,256]
// W_meta staged in smem once per block; each block handles B/gridDim batches.
// ---------------------------------------------------------------------------
__global__ void __launch_bounds__(256) meta_kernel(
        const float* __restrict__ th, const float* __restrict__ rf,
        const float* __restrict__ cs, const float* __restrict__ scl,
        const float* __restrict__ Wm, int B) {
    __shared__ float w[28 * Dm];
    __shared__ float f[28];
    for (int i = threadIdx.x; i < 28 * Dm; i += 256) w[i] = Wm[i];
    int d = threadIdx.x;
    for (int b = blockIdx.x; b < B; b += gridDim.x) {
        __syncthreads();
        if (d < 28) {
            float v;
            if (d < 8)       v = th[b * 8 + d];
            else if (d < 16) v = rf[b * 8 + (d - 8)];
            else if (d < 20) v = cs[b * 4 + (d - 16)];
            else             v = scl[b * 8 + (d - 20)];
            f[d] = v;
        }
        __syncthreads();
        float acc = 0.f;
        #pragma unroll
        for (int k = 0; k < 28; k++) acc = fmaf(f[k], w[k * Dm + d], acc);
        g_meta[b * Dm + d] = acc;
    }
}

// ---------------------------------------------------------------------------
// Kernel 2: main encoder. One block per batch row b, 256 threads.
// Thread owns d4 = tid&63 (a float4 of the 256-dim channel), loops over 16
// squares (s = tid>>6 + 4*it). Each warp has uniform s -> the 8 W_board row
// gathers are warp-uniform-index, fully coalesced 512B reads.
// ---------------------------------------------------------------------------
__global__ void __launch_bounds__(256) enc_kernel(
        const int*   __restrict__ bh,     // (B,8,64) piece codes
        const float* __restrict__ ep,     // (B,64)
        const int*   __restrict__ cat,    // (B,)
        const float* __restrict__ Wb,     // (105,256)
        const float* __restrict__ scale,  // (64,256)
        const float* __restrict__ tct,    // (8,256)
        float*       __restrict__ out) {  // (B,64,256)
    int b = blockIdx.x;
    __shared__ int   off[512];   // [s][h] -> (h*13+code)*256 element offset
    __shared__ float eps[64];
    int tid = threadIdx.x;

    const int* bhb = bh + b * 512;
    #pragma unroll
    for (int i = tid; i < 512; i += 256) {
        int h = i >> 6, s = i & 63;            // input layout is [h][s]
        off[s * 8 + h] = (h * 13 + bhb[i]) * Dm;
    }
    if (tid < 64) eps[tid] = ep[b * 64 + tid];
    __syncthreads();

    int dof = (tid & 63) * 4;
    float4 meta4 = *(const float4*)(g_meta + b * Dm + dof);
    float4 tc4   = *(const float4*)(tct + cat[b] * Dm + dof);
    float4 wep   = *(const float4*)(Wb + 104 * Dm + dof);  // ep row, hoisted
    const float* Wd = Wb + dof;
    float* outb = out + (long long)b * 64 * Dm + dof;
    int s0 = tid >> 6;

    // Fold tc into the per-thread additive constant applied after scaling:
    // out = (board+ep*Wep+meta)*scale + (pre + tc)
    #pragma unroll 2
    for (int it = 0; it < 16; it++) {
        int s = s0 + it * 4;
        const int* o = off + s * 8;
        float4 a0 = *(const float4*)(Wd + o[0]);
        float4 a1 = *(const float4*)(Wd + o[1]);
        float4 a2 = *(const float4*)(Wd + o[2]);
        float4 a3 = *(const float4*)(Wd + o[3]);
        float4 a4 = *(const float4*)(Wd + o[4]);
        float4 a5 = *(const float4*)(Wd + o[5]);
        float4 a6 = *(const float4*)(Wd + o[6]);
        float4 a7 = *(const float4*)(Wd + o[7]);
        float  e   = eps[s];
        float4 sc4 = *(const float4*)(scale + s * Dm + dof);
        float4 pr4 = *(const float4*)(g_pre + s * Dm + dof);

        float4 r;
        {
            float x = ((a0.x + a1.x) + (a2.x + a3.x)) + ((a4.x + a5.x) + (a6.x + a7.x));
            x = fmaf(e, wep.x, x) + meta4.x;
            r.x = fmaf(x, sc4.x, pr4.x + tc4.x);
        }
        {
            float x = ((a0.y + a1.y) + (a2.y + a3.y)) + ((a4.y + a5.y) + (a6.y + a7.y));
            x = fmaf(e, wep.y, x) + meta4.y;
            r.y = fmaf(x, sc4.y, pr4.y + tc4.y);
        }
        {
            float x = ((a0.z + a1.z) + (a2.z + a3.z)) + ((a4.z + a5.z) + (a6.z + a7.z));
            x = fmaf(e, wep.z, x) + meta4.z;
            r.z = fmaf(x, sc4.z, pr4.z + tc4.z);
        }
        {
            float x = ((a0.w + a1.w) + (a2.w + a3.w)) + ((a4.w + a5.w) + (a6.w + a7.w));
            x = fmaf(e, wep.w, x) + meta4.w;
            r.w = fmaf(x, sc4.w, pr4.w + tc4.w);
        }
        *(float4*)(outb + s * Dm) = r;
    }
}

// ---------------------------------------------------------------------------
extern "C" void kernel_launch(void* const* d_in, const int* in_sizes, int n_in,
                              void* d_out, int out_size) {
    const int*   bh  = (const int*)d_in[0];    // board_history
    const float* th  = (const float*)d_in[1];  // time_history
    const float* rf  = (const float*)d_in[2];  // rep_flags
    const float* cs  = (const float*)d_in[3];  // castling
    const float* ep  = (const float*)d_in[4];  // ep_mask
    const float* scl = (const float*)d_in[5];  // scalars
    const int*   cat = (const int*)d_in[6];    // tc_cat
    const float* Wb  = (const float*)d_in[7];  // W_board (105,256)
    const float* Wm  = (const float*)d_in[8];  // W_meta (28,256)
    const float* emb = (const float*)d_in[9];  // square_emb
    const float* ssc = (const float*)d_in[10]; // square_scale
    const float* sbi = (const float*)d_in[11]; // square_bias
    const float* tct = (const float*)d_in[12]; // tc_table

    float* out = (float*)d_out;
    int B = in_sizes[6];                       // tc_cat element count = batch

    pre_kernel<<<64, 256>>>(emb, ssc, sbi);
    meta_kernel<<<512, 256>>>(th, rf, cs, scl, Wm, B);
    enc_kernel<<<B, 256>>>(bh, ep, cat, Wb, ssc, tct, out);
}